// round 6
// baseline (speedup 1.0000x reference)
#include <cuda_runtime.h>
#include <cuda_bf16.h>
#include <math.h>

#define T_FRAMES 2000
#define NB 4
#define NHARM 6
#define T_AUD 960000
#define GRP 64
#define NG 15000                // 64-sample carry groups per batch
#define SCALE_POS (2000.0f/960000.0f)
#define INV_SR (1.0f/48000.0f)
#define TWO_PI_F 6.2831853071795864769f

#define CT 16                   // conv tile frames
#define NTILE 125               // 2000/16
#define CONV_BLOCKS (NTILE * NB)   // 500
#define TOT_BLOCKS 7500            // 60000 groups / 8 warps
#define W1_ELEMS (32 * 129 * 5)    // 20640
#define TRANS_BLOCKS 81            // ceil(20640/256)

// ---------------- scratch ----------------
__device__ float g_amp[NB * T_FRAMES * 8];   // padded [b][t][8], ch 0..5 valid
__device__ float g_wT[129 * 32 * 8];         // [ic][c][k(pad 8)]
__device__ float g_tot[NB * NG];
__device__ float g_carry[NB * NG];
__device__ float g_consts[16];               // [0..5]=A_h, [6..11]=B_h, [12]=nv, [13]=nu

__device__ __forceinline__ float tanh_approx(float x) {
    float y;
    asm("tanh.approx.f32 %0, %1;" : "=f"(y) : "f"(x));
    return y;
}

// ---------------- kernel 1: totals (64-sample groups) + weight transpose ----------------
__global__ void __launch_bounds__(256) prep_kernel(
    const float* __restrict__ f0, const float* __restrict__ w1)
{
    const int tid = threadIdx.x;
    if (blockIdx.x >= TOT_BLOCKS) {
        // weight transpose: w1[c][ic][k] -> g_wT[ic][c*8+k]
        int e = (blockIdx.x - TOT_BLOCKS) * 256 + tid;
        if (e < W1_ELEMS) {
            int c  = e / 645;
            int r  = e - c * 645;
            int ic = r / 5;
            int k  = r - ic * 5;
            g_wT[ic * 256 + c * 8 + k] = w1[e];
        }
        return;
    }
    // totals: warp = one 64-sample group, 2 samples per lane
    int warp = tid >> 5, lane = tid & 31;
    int gg = blockIdx.x * 8 + warp;            // 0..59999
    int b = gg / NG;
    int g = gg - b * NG;
    const float* f0b = f0 + b * T_FRAMES;
    int base = g * GRP + lane * 2;
    float s = 0.0f;
#pragma unroll
    for (int j = 0; j < 2; j++) {
        int i = base + j;
        float pos = fmaf((float)i + 0.5f, SCALE_POS, -0.5f);
        pos = fminf(fmaxf(pos, 0.0f), 1999.0f);
        int i0 = (int)pos;
        int i1 = min(i0 + 1, 1999);
        float w = pos - (float)i0;
        float v = f0b[i0] * (1.0f - w) + f0b[i1] * w;
        s += v * INV_SR;
    }
#pragma unroll
    for (int off = 16; off; off >>= 1)
        s += __shfl_down_sync(0xffffffffu, s, off);
    if (lane == 0) g_tot[b * NG + g] = s;
}

// ---------------- kernel 2: conv1 + SiLU + conv2 (transposed weights) ----------------
// block = 16-frame tile; 128 threads = 32 c x 4 tgroups (4 frames each)
__global__ void __launch_bounds__(128) conv_kernel(
    const float* __restrict__ f0, const float* __restrict__ mel,
    const float* __restrict__ b1,
    const float* __restrict__ w2, const float* __restrict__ b2)
{
    __shared__ float sx[129 * 20];   // frames t0-2 .. t0+17
    __shared__ float sh[32 * 16];
    const int bidx = blockIdx.x;
    const int b   = bidx / NTILE;
    const int t0  = (bidx - b * NTILE) * CT;
    const int tid = threadIdx.x;

    for (int e = tid; e < 129 * 20; e += 128) {
        int ic = e / 20, tt = e - ic * 20;
        int t = t0 + tt - 2;
        float v = 0.0f;
        if (t >= 0 && t < T_FRAMES)
            v = (ic == 0) ? f0[b * T_FRAMES + t]
                          : mel[(b * 128 + (ic - 1)) * T_FRAMES + t];
        sx[e] = v;
    }
    __syncthreads();

    const int c  = tid >> 2;        // channel 0..31
    const int tb = (tid & 3) * 4;   // base t_local 0,4,8,12

    float acc0, acc1, acc2, acc3;
    acc0 = acc1 = acc2 = acc3 = b1[c];

#pragma unroll 3
    for (int ic = 0; ic < 129; ic++) {
        float4 wa = *(const float4*)&g_wT[ic * 256 + c * 8];
        float  w4 = g_wT[ic * 256 + c * 8 + 4];
        float4 xa = *(const float4*)&sx[ic * 20 + tb];
        float4 xb = *(const float4*)&sx[ic * 20 + tb + 4];
        acc0 = fmaf(wa.x, xa.x, acc0); acc0 = fmaf(wa.y, xa.y, acc0);
        acc0 = fmaf(wa.z, xa.z, acc0); acc0 = fmaf(wa.w, xa.w, acc0);
        acc0 = fmaf(w4,  xb.x, acc0);
        acc1 = fmaf(wa.x, xa.y, acc1); acc1 = fmaf(wa.y, xa.z, acc1);
        acc1 = fmaf(wa.z, xa.w, acc1); acc1 = fmaf(wa.w, xb.x, acc1);
        acc1 = fmaf(w4,  xb.y, acc1);
        acc2 = fmaf(wa.x, xa.z, acc2); acc2 = fmaf(wa.y, xa.w, acc2);
        acc2 = fmaf(wa.z, xb.x, acc2); acc2 = fmaf(wa.w, xb.y, acc2);
        acc2 = fmaf(w4,  xb.z, acc2);
        acc3 = fmaf(wa.x, xa.w, acc3); acc3 = fmaf(wa.y, xb.x, acc3);
        acc3 = fmaf(wa.z, xb.y, acc3); acc3 = fmaf(wa.w, xb.z, acc3);
        acc3 = fmaf(w4,  xb.w, acc3);
    }
    sh[c * 16 + tb + 0] = acc0 / (1.0f + __expf(-acc0));
    sh[c * 16 + tb + 1] = acc1 / (1.0f + __expf(-acc1));
    sh[c * 16 + tb + 2] = acc2 / (1.0f + __expf(-acc2));
    sh[c * 16 + tb + 3] = acc3 / (1.0f + __expf(-acc3));
    __syncthreads();

    // conv2: 6 x 16 outputs
    if (tid < NHARM * 16) {
        int nh = tid >> 4, tl = tid & 15;
        int t = t0 + tl;
        float s = b2[nh];
        const float* wp = &w2[nh * 32];
#pragma unroll
        for (int cc = 0; cc < 32; cc++)
            s = fmaf(wp[cc], sh[cc * 16 + tl], s);
        g_amp[((size_t)b * T_FRAMES + t) * 8 + nh] = s;
    }
}

// ---------------- kernel 3: shuffle-based double exclusive wrapped scan ----------------
__global__ void __launch_bounds__(1024) scan_kernel(
    const float* __restrict__ als, const float* __restrict__ pho,
    const float* __restrict__ lnv, const float* __restrict__ lnu)
{
    const int b = blockIdx.x;
    const int tid = threadIdx.x;
    const int lane = tid & 31, wid = tid >> 5;
    const unsigned FULL = 0xffffffffu;

    if (b == 0 && tid < NHARM) {
        float e  = expf(als[tid]);
        float ph = TWO_PI_F * pho[tid];
        g_consts[tid]     = e * cosf(ph);
        g_consts[6 + tid] = e * sinf(ph);
        if (tid == 0) { g_consts[12] = expf(lnv[0]); g_consts[13] = expf(lnu[0]); }
    }

    const int PER = 16;                     // 1024*16 >= 15000
    const int s0 = tid * PER;
    float tl[PER];
    double loc = 0.0;
#pragma unroll
    for (int j = 0; j < PER; j++) {
        int idx = s0 + j;
        float t = (idx < NG) ? g_tot[b * NG + idx] : 0.0f;
        tl[j] = t;
        loc += (double)t;
    }
    double v = loc;
#pragma unroll
    for (int off = 1; off < 32; off <<= 1) {
        double n = __shfl_up_sync(FULL, v, off);
        if (lane >= off) v += n;
    }
    __shared__ double wsum[32];
    if (lane == 31) wsum[wid] = v;
    __syncthreads();
    if (wid == 0) {
        double x = wsum[lane];
#pragma unroll
        for (int off = 1; off < 32; off <<= 1) {
            double n = __shfl_up_sync(FULL, x, off);
            if (lane >= off) x += n;
        }
        wsum[lane] = x;
    }
    __syncthreads();
    double base = (v - loc) + (wid ? wsum[wid - 1] : 0.0);
#pragma unroll
    for (int j = 0; j < PER; j++) {
        int idx = s0 + j;
        if (idx < NG)
            g_carry[b * NG + idx] = (float)(base - floor(base));
        base += (double)tl[j];
    }
}

// ---------------- kernel 4: main synthesis ----------------
// 256 threads = 8 warps; warp = one 64-sample group; thread = 2 samples
__global__ void __launch_bounds__(256) main_kernel(
    const float* __restrict__ f0, const float* __restrict__ noise,
    float* __restrict__ out)
{
    const unsigned FULL = 0xffffffffu;
    const int wid  = threadIdx.x >> 5;
    const int lane = threadIdx.x & 31;
    const int gg   = blockIdx.x * 8 + wid;     // 0..59999
    const int b    = gg / NG;
    const int g    = gg - b * NG;
    const int base = g * GRP;

    // warp-uniform frame window F..F+2
    float pos0 = fmaf((float)base + 0.5f, SCALE_POS, -0.5f);
    pos0 = fmaxf(pos0, 0.0f);
    const int F = (int)pos0;

    // lane-predicated broadcast loads: 18 amp values + 3 f0 values
    float v = 0.0f;
    if (lane < 21) {
        if (lane < 18) {
            int rr = lane / 6;
            int ch = lane - rr * 6;
            int r  = min(F + rr, 1999);
            v = g_amp[((size_t)b * T_FRAMES + r) * 8 + ch];
        } else {
            int r = min(F + (lane - 18), 1999);
            v = f0[b * T_FRAMES + r];
        }
    }
    const float f0r0 = __shfl_sync(FULL, v, 18);
    const float f0r1 = __shfl_sync(FULL, v, 19);
    const float f0r2 = __shfl_sync(FULL, v, 20);

    float inc[2], f0v[2], wfr[2];
    int   dsel[2];
#pragma unroll
    for (int j = 0; j < 2; j++) {
        int i = base + lane * 2 + j;
        float pos = fmaf((float)i + 0.5f, SCALE_POS, -0.5f);
        pos = fminf(fmaxf(pos, 0.0f), 1999.0f);
        int i0 = (int)pos;
        float w = pos - (float)i0;
        int d = i0 - F;                         // 0 or 1
        dsel[j] = d; wfr[j] = w;
        float a = d ? f0r1 : f0r0;
        float c = d ? f0r2 : f0r1;
        float fv = a * (1.0f - w) + c * w;
        f0v[j] = fv;
        inc[j] = fv * INV_SR;
    }

    // warp inclusive scan of per-thread increment pairs
    float inc2 = inc[0] + inc[1];
    float sv = inc2;
#pragma unroll
    for (int off = 1; off < 32; off <<= 1) {
        float n = __shfl_up_sync(FULL, sv, off);
        if (lane >= off) sv += n;
    }
    float excl = g_carry[b * NG + g] + (sv - inc2);

    float s1[2], c1[2], voiced[2];
    {
        float ph0 = excl + inc[0];
        float r0  = ph0 - rintf(ph0);
        __sincosf(TWO_PI_F * r0, &s1[0], &c1[0]);
        float ph1 = ph0 + inc[1];
        float r1  = ph1 - rintf(ph1);
        __sincosf(TWO_PI_F * r1, &s1[1], &c1[1]);
        voiced[0] = (f0v[0] > 1.0f) ? 1.0f : 0.0f;
        voiced[1] = (f0v[1] > 1.0f) ? 1.0f : 0.0f;
    }

    const size_t off0 = (size_t)b * T_AUD + base + lane * 2;

    // noise channel (ch 6)
    {
        const float nv = g_consts[12], nu = g_consts[13];
        float2 nz = __ldcs((const float2*)(noise + off0));
        float2 o;
        o.x = nz.x * ((voiced[0] > 0.0f) ? nv : nu);
        o.y = nz.y * ((voiced[1] > 0.0f) ? nv : nu);
        __stcs((float2*)(out + (size_t)(b * 7 + 6) * T_AUD + base + lane * 2), o);
    }

    float sk[2] = {s1[0], s1[1]}, ck[2] = {c1[0], c1[1]};
#pragma unroll
    for (int h = 0; h < NHARM; h++) {
        if (h) {
#pragma unroll
            for (int j = 0; j < 2; j++) {
                float t = sk[j] * c1[j] + ck[j] * s1[j];
                ck[j] = ck[j] * c1[j] - sk[j] * s1[j];
                sk[j] = t;
            }
        }
        const float amA = __shfl_sync(FULL, v, h);
        const float amB = __shfl_sync(FULL, v, 6 + h);
        const float amC = __shfl_sync(FULL, v, 12 + h);
        const float cAh = g_consts[h];
        const float cBh = g_consts[6 + h];
        float2 o;
#pragma unroll
        for (int j = 0; j < 2; j++) {
            float a0 = dsel[j] ? amB : amA;
            float a1 = dsel[j] ? amC : amB;
            float am = a0 * (1.0f - wfr[j]) + a1 * wfr[j];
            float sig2 = 1.0f + tanh_approx(0.5f * am);
            float val = (sk[j] * cAh + ck[j] * cBh) * (sig2 * voiced[j]);
            (j ? o.y : o.x) = val;
        }
        __stcs((float2*)(out + (size_t)(b * 7 + h) * T_AUD + base + lane * 2), o);
    }
}

// ---------------- launcher ----------------
extern "C" void kernel_launch(void* const* d_in, const int* in_sizes, int n_in,
                              void* d_out, int out_size)
{
    const float* f0    = (const float*)d_in[0];
    const float* mel   = (const float*)d_in[1];
    const float* noise = (const float*)d_in[2];
    const float* w1    = (const float*)d_in[3];
    const float* b1    = (const float*)d_in[4];
    const float* w2    = (const float*)d_in[5];
    const float* b2    = (const float*)d_in[6];
    const float* als   = (const float*)d_in[7];
    const float* pho   = (const float*)d_in[8];
    const float* lnv   = (const float*)d_in[9];
    const float* lnu   = (const float*)d_in[10];
    float* out = (float*)d_out;

    prep_kernel<<<TOT_BLOCKS + TRANS_BLOCKS, 256>>>(f0, w1);
    conv_kernel<<<CONV_BLOCKS, 128>>>(f0, mel, b1, w2, b2);
    scan_kernel<<<NB, 1024>>>(als, pho, lnv, lnu);
    main_kernel<<<TOT_BLOCKS, 256>>>(f0, noise, out);
}

// round 7
// speedup vs baseline: 1.0792x; 1.0792x over previous
#include <cuda_runtime.h>
#include <cuda_bf16.h>
#include <math.h>

#define T_FRAMES 2000
#define NB 4
#define NHARM 6
#define T_AUD 960000
#define GRP 128
#define NG 7500                 // 128-sample carry groups per batch
#define SCALE_POS (2000.0f/960000.0f)
#define INV_SR (1.0f/48000.0f)
#define TWO_PI_F 6.2831853071795864769f

#define CT 24                   // conv tile frames
#define NTILE 84                // ceil(2000/24)
#define CONV_BLOCKS (NTILE * NB)   // 336
#define CONV_THREADS 192
#define TOT_BLOCKS 3750            // 30000 groups / 8 warps
#define W1_ELEMS (32 * 129 * 5)    // 20640
#define TRANS_BLOCKS 81            // ceil(20640/256)

// ---------------- scratch ----------------
__device__ float  g_amp[NB * T_FRAMES * 8];  // padded [b][t][8], ch 0..5 valid
__device__ float4 g_w4[129 * 32];            // w1 k=0..3, [ic][c]
__device__ float  g_w1s[129 * 32];           // w1 k=4,    [ic][c]
__device__ float  g_tot[NB * NG];
__device__ float  g_carry[NB * NG];
__device__ float  g_consts[16];              // [0..5]=A_h, [6..11]=B_h, [12]=nv, [13]=nu

__device__ __forceinline__ float tanh_approx(float x) {
    float y;
    asm("tanh.approx.f32 %0, %1;" : "=f"(y) : "f"(x));
    return y;
}

// ---------------- kernel 1: totals (128-sample groups) + weight transpose ----------------
__global__ void __launch_bounds__(256) prep_kernel(
    const float* __restrict__ f0, const float* __restrict__ w1)
{
    const int tid = threadIdx.x;
    if (blockIdx.x >= TOT_BLOCKS) {
        // transpose w1[c][ic][k] -> g_w4[ic*32+c] (k<4), g_w1s[ic*32+c] (k=4)
        int e = (blockIdx.x - TOT_BLOCKS) * 256 + tid;
        if (e < W1_ELEMS) {
            int c  = e / 645;
            int r  = e - c * 645;
            int ic = r / 5;
            int k  = r - ic * 5;
            float val = w1[e];
            if (k < 4) ((float*)g_w4)[(ic * 32 + c) * 4 + k] = val;
            else       g_w1s[ic * 32 + c] = val;
        }
        return;
    }
    // totals: warp = one 128-sample group, 4 samples per lane
    int warp = tid >> 5, lane = tid & 31;
    int gg = blockIdx.x * 8 + warp;            // 0..29999
    int b = gg / NG;
    int g = gg - b * NG;
    const float* f0b = f0 + b * T_FRAMES;
    int base = g * GRP + lane * 4;
    float s = 0.0f;
#pragma unroll
    for (int j = 0; j < 4; j++) {
        int i = base + j;
        float pos = fmaf((float)i + 0.5f, SCALE_POS, -0.5f);
        pos = fminf(fmaxf(pos, 0.0f), 1999.0f);
        int i0 = (int)pos;
        int i1 = min(i0 + 1, 1999);
        float w = pos - (float)i0;
        float v = f0b[i0] * (1.0f - w) + f0b[i1] * w;
        s += v * INV_SR;
    }
#pragma unroll
    for (int off = 16; off; off >>= 1)
        s += __shfl_down_sync(0xffffffffu, s, off);
    if (lane == 0) g_tot[b * NG + g] = s;
}

// ---------------- kernel 2: conv1 + SiLU + conv2, all-smem mainloop ----------------
// block = 24-frame tile, all 32 channels; 192 threads = lane-channel x 6 t-groups
// dynamic smem: sw4[4128] float4 | sw1[4128] float | sxx[129*28] float | sh[32*24] float
#define SMEM_CONV (4128*16 + 4128*4 + 129*28*4 + 32*24*4)
__global__ void __launch_bounds__(CONV_THREADS) conv_kernel(
    const float* __restrict__ f0, const float* __restrict__ mel,
    const float* __restrict__ b1,
    const float* __restrict__ w2, const float* __restrict__ b2)
{
    extern __shared__ char dyn[];
    float4* sw4 = (float4*)dyn;                      // 66048 B
    float*  sw1 = (float*)(dyn + 4128 * 16);         // 16512 B
    float*  sxx = sw1 + 4128;                        // 14448 B
    float*  sh  = sxx + 129 * 28;                    //  3072 B

    const int bidx = blockIdx.x;
    const int b   = bidx / NTILE;
    const int t0  = (bidx - b * NTILE) * CT;
    const int tid = threadIdx.x;

    // stage weights (coalesced) + x tile
    for (int i = tid; i < 4128; i += CONV_THREADS) {
        sw4[i] = g_w4[i];
        sw1[i] = g_w1s[i];
    }
    for (int e = tid; e < 129 * 28; e += CONV_THREADS) {
        int ic = e / 28, tt = e - ic * 28;
        int t = t0 + tt - 2;
        float v = 0.0f;
        if (t >= 0 && t < T_FRAMES)
            v = (ic == 0) ? f0[b * T_FRAMES + t]
                          : mel[(b * 128 + (ic - 1)) * T_FRAMES + t];
        sxx[e] = v;
    }
    __syncthreads();

    const int c  = tid & 31;        // channel = lane
    const int tb = (tid >> 5) * 4;  // base t_local 0,4,8,12,16,20

    float acc0, acc1, acc2, acc3;
    acc0 = acc1 = acc2 = acc3 = b1[c];

#pragma unroll 3
    for (int ic = 0; ic < 129; ic++) {
        float4 wa = sw4[ic * 32 + c];
        float  w4 = sw1[ic * 32 + c];
        float4 xa = *(const float4*)&sxx[ic * 28 + tb];
        float4 xb = *(const float4*)&sxx[ic * 28 + tb + 4];
        acc0 = fmaf(wa.x, xa.x, acc0); acc0 = fmaf(wa.y, xa.y, acc0);
        acc0 = fmaf(wa.z, xa.z, acc0); acc0 = fmaf(wa.w, xa.w, acc0);
        acc0 = fmaf(w4,  xb.x, acc0);
        acc1 = fmaf(wa.x, xa.y, acc1); acc1 = fmaf(wa.y, xa.z, acc1);
        acc1 = fmaf(wa.z, xa.w, acc1); acc1 = fmaf(wa.w, xb.x, acc1);
        acc1 = fmaf(w4,  xb.y, acc1);
        acc2 = fmaf(wa.x, xa.z, acc2); acc2 = fmaf(wa.y, xa.w, acc2);
        acc2 = fmaf(wa.z, xb.x, acc2); acc2 = fmaf(wa.w, xb.y, acc2);
        acc2 = fmaf(w4,  xb.z, acc2);
        acc3 = fmaf(wa.x, xa.w, acc3); acc3 = fmaf(wa.y, xb.x, acc3);
        acc3 = fmaf(wa.z, xb.y, acc3); acc3 = fmaf(wa.w, xb.z, acc3);
        acc3 = fmaf(w4,  xb.w, acc3);
    }
    sh[c * 24 + tb + 0] = acc0 / (1.0f + __expf(-acc0));
    sh[c * 24 + tb + 1] = acc1 / (1.0f + __expf(-acc1));
    sh[c * 24 + tb + 2] = acc2 / (1.0f + __expf(-acc2));
    sh[c * 24 + tb + 3] = acc3 / (1.0f + __expf(-acc3));
    __syncthreads();

    // conv2: 6 x 24 outputs
    if (tid < NHARM * CT) {
        int nh = tid / CT, tl = tid - nh * CT;
        int t = t0 + tl;
        if (t < T_FRAMES) {
            float s = b2[nh];
            const float* wp = &w2[nh * 32];
#pragma unroll
            for (int cc = 0; cc < 32; cc++)
                s = fmaf(__ldg(wp + cc), sh[cc * 24 + tl], s);
            g_amp[((size_t)b * T_FRAMES + t) * 8 + nh] = s;
        }
    }
}

// ---------------- kernel 3: shuffle-based double exclusive wrapped scan ----------------
__global__ void __launch_bounds__(1024) scan_kernel(
    const float* __restrict__ als, const float* __restrict__ pho,
    const float* __restrict__ lnv, const float* __restrict__ lnu)
{
    const int b = blockIdx.x;
    const int tid = threadIdx.x;
    const int lane = tid & 31, wid = tid >> 5;
    const unsigned FULL = 0xffffffffu;

    if (b == 0 && tid < NHARM) {
        float e  = expf(als[tid]);
        float ph = TWO_PI_F * pho[tid];
        g_consts[tid]     = e * cosf(ph);
        g_consts[6 + tid] = e * sinf(ph);
        if (tid == 0) { g_consts[12] = expf(lnv[0]); g_consts[13] = expf(lnu[0]); }
    }

    const int PER = 8;                      // 1024*8 >= 7500
    const int s0 = tid * PER;
    float tl[PER];
    double loc = 0.0;
#pragma unroll
    for (int j = 0; j < PER; j++) {
        int idx = s0 + j;
        float t = (idx < NG) ? g_tot[b * NG + idx] : 0.0f;
        tl[j] = t;
        loc += (double)t;
    }
    double v = loc;
#pragma unroll
    for (int off = 1; off < 32; off <<= 1) {
        double n = __shfl_up_sync(FULL, v, off);
        if (lane >= off) v += n;
    }
    __shared__ double wsum[32];
    if (lane == 31) wsum[wid] = v;
    __syncthreads();
    if (wid == 0) {
        double x = wsum[lane];
#pragma unroll
        for (int off = 1; off < 32; off <<= 1) {
            double n = __shfl_up_sync(FULL, x, off);
            if (lane >= off) x += n;
        }
        wsum[lane] = x;
    }
    __syncthreads();
    double base = (v - loc) + (wid ? wsum[wid - 1] : 0.0);
#pragma unroll
    for (int j = 0; j < PER; j++) {
        int idx = s0 + j;
        if (idx < NG)
            g_carry[b * NG + idx] = (float)(base - floor(base));
        base += (double)tl[j];
    }
}

// ---------------- kernel 4: main synthesis (R4 structure + tanh sigmoid) ----------------
// block = 128 threads; warp = one 128-sample group; thread = 4 samples
__global__ void __launch_bounds__(128) main_kernel(
    const float* __restrict__ f0, const float* __restrict__ noise,
    float* __restrict__ out)
{
    const int b    = blockIdx.y;
    const int warp = threadIdx.x >> 5;
    const int lane = threadIdx.x & 31;
    const int g    = blockIdx.x * 4 + warp;       // carry group 0..7499
    const int base = g * GRP + lane * 4;
    const float* f0b = f0 + b * T_FRAMES;

    float inc[4], f0v[4], wfr[4];
    int   ia[4];
#pragma unroll
    for (int j = 0; j < 4; j++) {
        int i = base + j;
        float pos = fmaf((float)i + 0.5f, SCALE_POS, -0.5f);
        pos = fminf(fmaxf(pos, 0.0f), 1999.0f);
        int i0 = (int)pos;
        int i1 = min(i0 + 1, 1999);
        float w = pos - (float)i0;
        ia[j] = i0; wfr[j] = w;
        float v = f0b[i0] * (1.0f - w) + f0b[i1] * w;
        f0v[j] = v;
        inc[j] = v * INV_SR;
    }

    float inc4 = ((inc[0] + inc[1]) + inc[2]) + inc[3];
    const unsigned FULL = 0xffffffffu;
    float v = inc4;
#pragma unroll
    for (int off = 1; off < 32; off <<= 1) {
        float n = __shfl_up_sync(FULL, v, off);
        if (lane >= off) v += n;
    }
    float running = g_carry[b * NG + g] + (v - inc4);   // exclusive prefix + carry

    float cA[6], cB[6];
#pragma unroll
    for (int h = 0; h < 6; h++) { cA[h] = g_consts[h]; cB[h] = g_consts[6 + h]; }
    const float nv = g_consts[12], nu = g_consts[13];

    float4 nz = *(const float4*)(noise + (size_t)b * T_AUD + base);
    const float* nzp = &nz.x;

    float och[7][4];
#pragma unroll
    for (int j = 0; j < 4; j++) {
        running += inc[j];
        float r  = running - rintf(running);           // [-0.5, 0.5], periodic-1
        float s1, c1;
        __sincosf(TWO_PI_F * r, &s1, &c1);
        float voiced = (f0v[j] > 1.0f) ? 1.0f : 0.0f;

        const float* ap = g_amp + ((size_t)b * T_FRAMES + ia[j]) * 8;
        int i1 = min(ia[j] + 1, 1999);
        const float* aq = g_amp + ((size_t)b * T_FRAMES + i1) * 8;
        float4 u0 = *(const float4*)ap;
        float4 u1 = *(const float4*)(ap + 4);
        float4 p0 = *(const float4*)aq;
        float4 p1 = *(const float4*)(aq + 4);
        float w = wfr[j], iw = 1.0f - w;
        float am[6] = { u0.x * iw + p0.x * w, u0.y * iw + p0.y * w,
                        u0.z * iw + p0.z * w, u0.w * iw + p0.w * w,
                        u1.x * iw + p1.x * w, u1.y * iw + p1.y * w };

        float sk = s1, ck = c1;
#pragma unroll
        for (int h = 0; h < 6; h++) {
            if (h) {
                float t = sk * c1 + ck * s1;
                ck = ck * c1 - sk * s1;
                sk = t;
            }
            float sig2 = 1.0f + tanh_approx(0.5f * am[h]);  // 2*sigmoid(am)
            och[h][j] = (sk * cA[h] + ck * cB[h]) * (sig2 * voiced);
        }
        float na = (voiced > 0.0f) ? nv : nu;
        och[6][j] = nzp[j] * na;
    }

#pragma unroll
    for (int h = 0; h < 7; h++) {
        float4 o = make_float4(och[h][0], och[h][1], och[h][2], och[h][3]);
        *(float4*)(out + ((size_t)(b * 7 + h)) * T_AUD + base) = o;
    }
}

// ---------------- launcher ----------------
extern "C" void kernel_launch(void* const* d_in, const int* in_sizes, int n_in,
                              void* d_out, int out_size)
{
    const float* f0    = (const float*)d_in[0];
    const float* mel   = (const float*)d_in[1];
    const float* noise = (const float*)d_in[2];
    const float* w1    = (const float*)d_in[3];
    const float* b1    = (const float*)d_in[4];
    const float* w2    = (const float*)d_in[5];
    const float* b2    = (const float*)d_in[6];
    const float* als   = (const float*)d_in[7];
    const float* pho   = (const float*)d_in[8];
    const float* lnv   = (const float*)d_in[9];
    const float* lnu   = (const float*)d_in[10];
    float* out = (float*)d_out;

    static int smem_set = 0;
    if (!smem_set) {
        cudaFuncSetAttribute(conv_kernel,
                             cudaFuncAttributeMaxDynamicSharedMemorySize, SMEM_CONV);
        smem_set = 1;
    }

    prep_kernel<<<TOT_BLOCKS + TRANS_BLOCKS, 256>>>(f0, w1);
    conv_kernel<<<CONV_BLOCKS, CONV_THREADS, SMEM_CONV>>>(f0, mel, b1, w2, b2);
    scan_kernel<<<NB, 1024>>>(als, pho, lnv, lnu);
    main_kernel<<<dim3(1875, NB), 128>>>(f0, noise, out);
}

// round 8
// speedup vs baseline: 1.0922x; 1.0121x over previous
#include <cuda_runtime.h>
#include <cuda_bf16.h>
#include <math.h>

#define T_FRAMES 2000
#define NB 4
#define NHARM 6
#define T_AUD 960000
#define GRP 128
#define NG 7500                 // 128-sample carry groups per batch
#define SCALE_POS (2000.0f/960000.0f)
#define INV_SR (1.0f/48000.0f)
#define TWO_PI_F 6.2831853071795864769f

#define CT 24                   // conv tile frames
#define NTILE 84                // ceil(2000/24)
#define CONV_BLOCKS (NTILE * NB)   // 336
#define CONV_THREADS 192
#define TOT_BLOCKS 3750            // 30000 groups / 8 warps
#define W1_ELEMS (32 * 129 * 5)    // 20640

// ---------------- scratch ----------------
__device__ float g_amp[NB * T_FRAMES * 8];   // padded [b][t][8], ch 0..5 valid
__device__ float g_tot[NB * NG];
__device__ float g_carry[NB * NG];
__device__ float g_consts[16];               // [0..5]=A_h, [6..11]=B_h, [12]=nv, [13]=nu

__device__ __forceinline__ float tanh_approx(float x) {
    float y;
    asm("tanh.approx.f32 %0, %1;" : "=f"(y) : "f"(x));
    return y;
}

// ---------------- kernel 1: per-group phase-increment totals ----------------
// no smem, full occupancy; warp = one 128-sample group, 4 samples/lane
__global__ void __launch_bounds__(256) totals_kernel(const float* __restrict__ f0)
{
    int warp = threadIdx.x >> 5, lane = threadIdx.x & 31;
    int gg = blockIdx.x * 8 + warp;            // 0..29999
    int b = gg / NG;
    int g = gg - b * NG;
    const float* f0b = f0 + b * T_FRAMES;
    int base = g * GRP + lane * 4;
    float s = 0.0f;
#pragma unroll
    for (int j = 0; j < 4; j++) {
        int i = base + j;
        float pos = fmaf((float)i + 0.5f, SCALE_POS, -0.5f);
        pos = fminf(fmaxf(pos, 0.0f), 1999.0f);
        int i0 = (int)pos;
        int i1 = min(i0 + 1, 1999);
        float w = pos - (float)i0;
        float v = f0b[i0] * (1.0f - w) + f0b[i1] * w;
        s += v * INV_SR;
    }
#pragma unroll
    for (int off = 16; off; off >>= 1)
        s += __shfl_down_sync(0xffffffffu, s, off);
    if (lane == 0) g_tot[b * NG + g] = s;
}

// ---------------- kernel 2: conv1 + SiLU + conv2, raw weights staged in smem ----------------
// block = 24-frame tile, all 32 channels; 192 threads = lane-channel x 6 t-groups
// dynamic smem: swr[20640] | sxx[129*28] | sh[32*24]
#define SMEM_CONV (W1_ELEMS*4 + 129*28*4 + 32*24*4)
__global__ void __launch_bounds__(CONV_THREADS) conv_kernel(
    const float* __restrict__ f0, const float* __restrict__ mel,
    const float* __restrict__ w1, const float* __restrict__ b1,
    const float* __restrict__ w2, const float* __restrict__ b2)
{
    extern __shared__ char dyn[];
    float* swr = (float*)dyn;                 // 82560 B, raw w1 [c][ic][k]
    float* sxx = swr + W1_ELEMS;              // 14448 B
    float* sh  = sxx + 129 * 28;              //  3072 B

    const int bidx = blockIdx.x;
    const int b   = bidx / NTILE;
    const int t0  = (bidx - b * NTILE) * CT;
    const int tid = threadIdx.x;

    // stage raw weights coalesced (float4; 20640 = 5160 float4s)
    {
        const float4* src = (const float4*)w1;
        float4* dst = (float4*)swr;
        for (int i = tid; i < W1_ELEMS / 4; i += CONV_THREADS)
            dst[i] = src[i];
    }
    for (int e = tid; e < 129 * 28; e += CONV_THREADS) {
        int ic = e / 28, tt = e - ic * 28;
        int t = t0 + tt - 2;
        float v = 0.0f;
        if (t >= 0 && t < T_FRAMES)
            v = (ic == 0) ? f0[b * T_FRAMES + t]
                          : mel[(b * 128 + (ic - 1)) * T_FRAMES + t];
        sxx[e] = v;
    }
    __syncthreads();

    const int c  = tid & 31;        // channel = lane -> conflict-free weight LDS
    const int tb = (tid >> 5) * 4;  // base t_local 0,4,8,12,16,20 (warp-uniform)

    float acc0, acc1, acc2, acc3;
    acc0 = acc1 = acc2 = acc3 = b1[c];

    const float* wrow = swr + c * 645;        // [ic*5 + k]
#pragma unroll 3
    for (int ic = 0; ic < 129; ic++) {
        float w0 = wrow[ic * 5 + 0];
        float w1v = wrow[ic * 5 + 1];
        float w2v = wrow[ic * 5 + 2];
        float w3 = wrow[ic * 5 + 3];
        float w4 = wrow[ic * 5 + 4];
        float4 xa = *(const float4*)&sxx[ic * 28 + tb];
        float4 xb = *(const float4*)&sxx[ic * 28 + tb + 4];
        acc0 = fmaf(w0, xa.x, acc0); acc0 = fmaf(w1v, xa.y, acc0);
        acc0 = fmaf(w2v, xa.z, acc0); acc0 = fmaf(w3, xa.w, acc0);
        acc0 = fmaf(w4, xb.x, acc0);
        acc1 = fmaf(w0, xa.y, acc1); acc1 = fmaf(w1v, xa.z, acc1);
        acc1 = fmaf(w2v, xa.w, acc1); acc1 = fmaf(w3, xb.x, acc1);
        acc1 = fmaf(w4, xb.y, acc1);
        acc2 = fmaf(w0, xa.z, acc2); acc2 = fmaf(w1v, xa.w, acc2);
        acc2 = fmaf(w2v, xb.x, acc2); acc2 = fmaf(w3, xb.y, acc2);
        acc2 = fmaf(w4, xb.z, acc2);
        acc3 = fmaf(w0, xa.w, acc3); acc3 = fmaf(w1v, xb.x, acc3);
        acc3 = fmaf(w2v, xb.y, acc3); acc3 = fmaf(w3, xb.z, acc3);
        acc3 = fmaf(w4, xb.w, acc3);
    }
    sh[c * 24 + tb + 0] = acc0 / (1.0f + __expf(-acc0));
    sh[c * 24 + tb + 1] = acc1 / (1.0f + __expf(-acc1));
    sh[c * 24 + tb + 2] = acc2 / (1.0f + __expf(-acc2));
    sh[c * 24 + tb + 3] = acc3 / (1.0f + __expf(-acc3));
    __syncthreads();

    // conv2: 6 x 24 outputs
    if (tid < NHARM * CT) {
        int nh = tid / CT, tl = tid - nh * CT;
        int t = t0 + tl;
        if (t < T_FRAMES) {
            float s = b2[nh];
            const float* wp = &w2[nh * 32];
#pragma unroll
            for (int cc = 0; cc < 32; cc++)
                s = fmaf(__ldg(wp + cc), sh[cc * 24 + tl], s);
            g_amp[((size_t)b * T_FRAMES + t) * 8 + nh] = s;
        }
    }
}

// ---------------- kernel 3: shuffle-based double exclusive wrapped scan ----------------
__global__ void __launch_bounds__(1024) scan_kernel(
    const float* __restrict__ als, const float* __restrict__ pho,
    const float* __restrict__ lnv, const float* __restrict__ lnu)
{
    const int b = blockIdx.x;
    const int tid = threadIdx.x;
    const int lane = tid & 31, wid = tid >> 5;
    const unsigned FULL = 0xffffffffu;

    if (b == 0 && tid < NHARM) {
        float e  = expf(als[tid]);
        float ph = TWO_PI_F * pho[tid];
        g_consts[tid]     = e * cosf(ph);
        g_consts[6 + tid] = e * sinf(ph);
        if (tid == 0) { g_consts[12] = expf(lnv[0]); g_consts[13] = expf(lnu[0]); }
    }

    const int PER = 8;                      // 1024*8 >= 7500
    const int s0 = tid * PER;
    float tl[PER];
    double loc = 0.0;
#pragma unroll
    for (int j = 0; j < PER; j++) {
        int idx = s0 + j;
        float t = (idx < NG) ? g_tot[b * NG + idx] : 0.0f;
        tl[j] = t;
        loc += (double)t;
    }
    double v = loc;
#pragma unroll
    for (int off = 1; off < 32; off <<= 1) {
        double n = __shfl_up_sync(FULL, v, off);
        if (lane >= off) v += n;
    }
    __shared__ double wsum[32];
    if (lane == 31) wsum[wid] = v;
    __syncthreads();
    if (wid == 0) {
        double x = wsum[lane];
#pragma unroll
        for (int off = 1; off < 32; off <<= 1) {
            double n = __shfl_up_sync(FULL, x, off);
            if (lane >= off) x += n;
        }
        wsum[lane] = x;
    }
    __syncthreads();
    double base = (v - loc) + (wid ? wsum[wid - 1] : 0.0);
#pragma unroll
    for (int j = 0; j < PER; j++) {
        int idx = s0 + j;
        if (idx < NG)
            g_carry[b * NG + idx] = (float)(base - floor(base));
        base += (double)tl[j];
    }
}

// ---------------- kernel 4: main synthesis ----------------
// block = 128 threads; warp = one 128-sample group; thread = 4 samples
__global__ void __launch_bounds__(128) main_kernel(
    const float* __restrict__ f0, const float* __restrict__ noise,
    float* __restrict__ out)
{
    const int b    = blockIdx.y;
    const int warp = threadIdx.x >> 5;
    const int lane = threadIdx.x & 31;
    const int g    = blockIdx.x * 4 + warp;       // carry group 0..7499
    const int base = g * GRP + lane * 4;
    const float* f0b = f0 + b * T_FRAMES;

    float inc[4], f0v[4], wfr[4];
    int   ia[4];
#pragma unroll
    for (int j = 0; j < 4; j++) {
        int i = base + j;
        float pos = fmaf((float)i + 0.5f, SCALE_POS, -0.5f);
        pos = fminf(fmaxf(pos, 0.0f), 1999.0f);
        int i0 = (int)pos;
        int i1 = min(i0 + 1, 1999);
        float w = pos - (float)i0;
        ia[j] = i0; wfr[j] = w;
        float v = f0b[i0] * (1.0f - w) + f0b[i1] * w;
        f0v[j] = v;
        inc[j] = v * INV_SR;
    }

    float inc4 = ((inc[0] + inc[1]) + inc[2]) + inc[3];
    const unsigned FULL = 0xffffffffu;
    float v = inc4;
#pragma unroll
    for (int off = 1; off < 32; off <<= 1) {
        float n = __shfl_up_sync(FULL, v, off);
        if (lane >= off) v += n;
    }
    float running = g_carry[b * NG + g] + (v - inc4);   // exclusive prefix + carry

    float cA[6], cB[6];
#pragma unroll
    for (int h = 0; h < 6; h++) { cA[h] = g_consts[h]; cB[h] = g_consts[6 + h]; }
    const float nv = g_consts[12], nu = g_consts[13];

    float4 nz = *(const float4*)(noise + (size_t)b * T_AUD + base);
    const float* nzp = &nz.x;

    float och[7][4];
#pragma unroll
    for (int j = 0; j < 4; j++) {
        running += inc[j];
        float r  = running - rintf(running);           // [-0.5, 0.5], periodic-1
        float s1, c1;
        __sincosf(TWO_PI_F * r, &s1, &c1);
        float voiced = (f0v[j] > 1.0f) ? 1.0f : 0.0f;

        const float* ap = g_amp + ((size_t)b * T_FRAMES + ia[j]) * 8;
        int i1 = min(ia[j] + 1, 1999);
        const float* aq = g_amp + ((size_t)b * T_FRAMES + i1) * 8;
        float4 u0 = *(const float4*)ap;
        float4 u1 = *(const float4*)(ap + 4);
        float4 p0 = *(const float4*)aq;
        float4 p1 = *(const float4*)(aq + 4);
        float w = wfr[j], iw = 1.0f - w;
        float am[6] = { u0.x * iw + p0.x * w, u0.y * iw + p0.y * w,
                        u0.z * iw + p0.z * w, u0.w * iw + p0.w * w,
                        u1.x * iw + p1.x * w, u1.y * iw + p1.y * w };

        float sk = s1, ck = c1;
#pragma unroll
        for (int h = 0; h < 6; h++) {
            if (h) {
                float t = sk * c1 + ck * s1;
                ck = ck * c1 - sk * s1;
                sk = t;
            }
            float sig2 = 1.0f + tanh_approx(0.5f * am[h]);  // 2*sigmoid(am)
            och[h][j] = (sk * cA[h] + ck * cB[h]) * (sig2 * voiced);
        }
        float na = (voiced > 0.0f) ? nv : nu;
        och[6][j] = nzp[j] * na;
    }

#pragma unroll
    for (int h = 0; h < 7; h++) {
        float4 o = make_float4(och[h][0], och[h][1], och[h][2], och[h][3]);
        *(float4*)(out + ((size_t)(b * 7 + h)) * T_AUD + base) = o;
    }
}

// ---------------- launcher ----------------
extern "C" void kernel_launch(void* const* d_in, const int* in_sizes, int n_in,
                              void* d_out, int out_size)
{
    const float* f0    = (const float*)d_in[0];
    const float* mel   = (const float*)d_in[1];
    const float* noise = (const float*)d_in[2];
    const float* w1    = (const float*)d_in[3];
    const float* b1    = (const float*)d_in[4];
    const float* w2    = (const float*)d_in[5];
    const float* b2    = (const float*)d_in[6];
    const float* als   = (const float*)d_in[7];
    const float* pho   = (const float*)d_in[8];
    const float* lnv   = (const float*)d_in[9];
    const float* lnu   = (const float*)d_in[10];
    float* out = (float*)d_out;

    cudaFuncSetAttribute(conv_kernel,
                         cudaFuncAttributeMaxDynamicSharedMemorySize, SMEM_CONV);

    totals_kernel<<<TOT_BLOCKS, 256>>>(f0);
    conv_kernel<<<CONV_BLOCKS, CONV_THREADS, SMEM_CONV>>>(f0, mel, w1, b1, w2, b2);
    scan_kernel<<<NB, 1024>>>(als, pho, lnv, lnu);
    main_kernel<<<dim3(1875, NB), 128>>>(f0, noise, out);
}

// round 10
// speedup vs baseline: 1.4659x; 1.3421x over previous
#include <cuda_runtime.h>
#include <cuda_bf16.h>
#include <math.h>

#define T_FRAMES 2000
#define NB 4
#define NHARM 6
#define T_AUD 960000
#define GRP 128
#define NG 7500                  // 128-sample groups per batch
#define NGTOT 30000
#define SCALE_POS (2000.0f/960000.0f)
#define INV_SR (1.0f/48000.0f)
#define TWO_PI_F 6.2831853071795864769f

#define NBLOCKS 444              // 3 * 148: single wave, all resident
#define NWARPS_G (NBLOCKS * 8)   // 3552
#define CONV_NB 252              // 63 tiles x 4 batches, 32 frames/tile
#define W1_ELEMS (32 * 129 * 5)  // 20640

// ---------------- scratch ----------------
__device__ float  g_amp[NB * T_FRAMES * 8];  // [b][t][8], ch 0..5 valid
__device__ float4 g_w4[129 * 32];            // w1 k=0..3, [ic][c]
__device__ float  g_w1s[129 * 32];           // w1 k=4,    [ic][c]
__device__ float  g_tot[NB * NG];
__device__ float  g_carry[NB * NG];
__device__ float  g_consts[16];              // [0..5]=A, [6..11]=B, [12]=nv, [13]=nu
__device__ unsigned g_cnt;                   // barrier counter (returns to 0)
__device__ volatile unsigned g_sense;        // barrier sense (returns to 0)

__device__ __forceinline__ float tanh_approx(float x) {
    float y;
    asm("tanh.approx.f32 %0, %1;" : "=f"(y) : "f"(x));
    return y;
}

__device__ __forceinline__ void grid_barrier(unsigned target) {
    __syncthreads();
    if (threadIdx.x == 0) {
        __threadfence();
        unsigned old = atomicAdd(&g_cnt, 1u);
        if (old == NBLOCKS - 1) {
            *(volatile unsigned*)&g_cnt = 0u;
            __threadfence();
            g_sense = target;
        } else {
            while (g_sense != target) __nanosleep(32);
            __threadfence();
        }
    }
    __syncthreads();
}

__global__ void __launch_bounds__(256, 4) fused_kernel(
    const float* __restrict__ f0, const float* __restrict__ mel,
    const float* __restrict__ noise,
    const float* __restrict__ w1, const float* __restrict__ b1,
    const float* __restrict__ w2, const float* __restrict__ b2,
    const float* __restrict__ als, const float* __restrict__ pho,
    const float* __restrict__ lnv, const float* __restrict__ lnu,
    float* __restrict__ out)
{
    __shared__ float  sxx[129 * 36];
    __shared__ float  sh[32 * 32];
    __shared__ double wsum[8];

    const int bid  = blockIdx.x;
    const int tid  = threadIdx.x;
    const int wid  = tid >> 5;
    const int lane = tid & 31;
    const unsigned FULL = 0xffffffffu;

    // ================= PHASE 1: totals + weight transpose + consts =================
    if (bid < 81) {
        int e = bid * 256 + tid;
        if (e < W1_ELEMS) {
            int c  = e / 645;
            int r  = e - c * 645;
            int ic = r / 5;
            int k  = r - ic * 5;
            float val = w1[e];
            if (k < 4) ((float*)g_w4)[(ic * 32 + c) * 4 + k] = val;
            else       g_w1s[ic * 32 + c] = val;
        }
    }
    if (bid == 256 && tid < NHARM) {
        float e  = expf(als[tid]);
        float ph = TWO_PI_F * pho[tid];
        g_consts[tid]     = e * cosf(ph);
        g_consts[6 + tid] = e * sinf(ph);
        if (tid == 0) { g_consts[12] = expf(lnv[0]); g_consts[13] = expf(lnu[0]); }
    }
    for (int gg = bid * 8 + wid; gg < NGTOT; gg += NWARPS_G) {
        int b = gg / NG;
        int g = gg - b * NG;
        const float* f0b = f0 + b * T_FRAMES;
        int base = g * GRP + lane * 4;
        float s = 0.0f;
#pragma unroll
        for (int j = 0; j < 4; j++) {
            int i = base + j;
            float pos = fmaf((float)i + 0.5f, SCALE_POS, -0.5f);
            pos = fminf(fmaxf(pos, 0.0f), 1999.0f);
            int i0 = (int)pos;
            int i1 = min(i0 + 1, 1999);
            float w = pos - (float)i0;
            float v = f0b[i0] * (1.0f - w) + f0b[i1] * w;
            s += v * INV_SR;
        }
#pragma unroll
        for (int off = 16; off; off >>= 1)
            s += __shfl_down_sync(FULL, s, off);
        if (lane == 0) g_tot[b * NG + g] = s;
    }

    grid_barrier(1u);

    // ================= PHASE 2: conv (252 blocks) || scan (4 blocks) =================
    if (bid < CONV_NB) {
        const int b  = bid / 63;
        const int t0 = (bid - b * 63) * 32;

        for (int e = tid; e < 129 * 36; e += 256) {
            int ic = e / 36, tt = e - ic * 36;
            int t = t0 + tt - 2;
            float v = 0.0f;
            if (t >= 0 && t < T_FRAMES)
                v = (ic == 0) ? f0[b * T_FRAMES + t]
                              : mel[(b * 128 + (ic - 1)) * T_FRAMES + t];
            sxx[e] = v;
        }
        __syncthreads();

        const int c  = tid & 31;        // channel = lane -> coalesced weight LDG
        const int tb = (tid >> 5) * 4;  // frames tb..tb+3 (warp-uniform)

        float acc0, acc1, acc2, acc3;
        acc0 = acc1 = acc2 = acc3 = b1[c];

#pragma unroll 3
        for (int ic = 0; ic < 129; ic++) {
            float4 wa = __ldg(&g_w4[ic * 32 + c]);
            float  w4 = __ldg(&g_w1s[ic * 32 + c]);
            float4 xa = *(const float4*)&sxx[ic * 36 + tb];
            float4 xb = *(const float4*)&sxx[ic * 36 + tb + 4];
            acc0 = fmaf(wa.x, xa.x, acc0); acc0 = fmaf(wa.y, xa.y, acc0);
            acc0 = fmaf(wa.z, xa.z, acc0); acc0 = fmaf(wa.w, xa.w, acc0);
            acc0 = fmaf(w4,  xb.x, acc0);
            acc1 = fmaf(wa.x, xa.y, acc1); acc1 = fmaf(wa.y, xa.z, acc1);
            acc1 = fmaf(wa.z, xa.w, acc1); acc1 = fmaf(wa.w, xb.x, acc1);
            acc1 = fmaf(w4,  xb.y, acc1);
            acc2 = fmaf(wa.x, xa.z, acc2); acc2 = fmaf(wa.y, xa.w, acc2);
            acc2 = fmaf(wa.z, xb.x, acc2); acc2 = fmaf(wa.w, xb.y, acc2);
            acc2 = fmaf(w4,  xb.z, acc2);
            acc3 = fmaf(wa.x, xa.w, acc3); acc3 = fmaf(wa.y, xb.x, acc3);
            acc3 = fmaf(wa.z, xb.y, acc3); acc3 = fmaf(wa.w, xb.z, acc3);
            acc3 = fmaf(w4,  xb.w, acc3);
        }
        sh[c * 32 + tb + 0] = acc0 / (1.0f + __expf(-acc0));
        sh[c * 32 + tb + 1] = acc1 / (1.0f + __expf(-acc1));
        sh[c * 32 + tb + 2] = acc2 / (1.0f + __expf(-acc2));
        sh[c * 32 + tb + 3] = acc3 / (1.0f + __expf(-acc3));
        __syncthreads();

        if (tid < NHARM * 32) {
            int nh = tid >> 5, tl = tid & 31;
            int t = t0 + tl;
            if (t < T_FRAMES) {
                float s = b2[nh];
                const float* wp = &w2[nh * 32];
#pragma unroll
                for (int cc = 0; cc < 32; cc++)
                    s = fmaf(__ldg(wp + cc), sh[cc * 32 + tl], s);
                g_amp[((size_t)b * T_FRAMES + t) * 8 + nh] = s;
            }
        }
    } else if (bid < CONV_NB + NB) {
        // ---- scan role: one block per batch, 256 threads, PER=30 ----
        const int b = bid - CONV_NB;
        const int PER = 30;                    // 256*30 >= 7500
        const int s0 = tid * PER;
        float tl[PER];
        double loc = 0.0;
#pragma unroll
        for (int j = 0; j < PER; j++) {
            int idx = s0 + j;
            float t = (idx < NG) ? g_tot[b * NG + idx] : 0.0f;
            tl[j] = t;
            loc += (double)t;
        }
        double v = loc;
#pragma unroll
        for (int off = 1; off < 32; off <<= 1) {
            double n = __shfl_up_sync(FULL, v, off);
            if (lane >= off) v += n;
        }
        if (lane == 31) wsum[wid] = v;
        __syncthreads();
        if (wid == 0 && lane < 8) {
            double x = wsum[lane];
#pragma unroll
            for (int off = 1; off < 8; off <<= 1) {
                double n = __shfl_up_sync(0xffu, x, off);
                if (lane >= off) x += n;
            }
            wsum[lane] = x;
        }
        __syncthreads();
        double base = (v - loc) + (wid ? wsum[wid - 1] : 0.0);
#pragma unroll
        for (int j = 0; j < PER; j++) {
            int idx = s0 + j;
            if (idx < NG)
                g_carry[b * NG + idx] = (float)(base - floor(base));
            base += (double)tl[j];
        }
    }

    grid_barrier(0u);

    // ================= PHASE 3: main synthesis =================
    float cA[6], cB[6];
#pragma unroll
    for (int h = 0; h < 6; h++) { cA[h] = g_consts[h]; cB[h] = g_consts[6 + h]; }
    const float nvs = g_consts[12], nus = g_consts[13];

    for (int gg = bid * 8 + wid; gg < NGTOT; gg += NWARPS_G) {
        const int b    = gg / NG;
        const int g    = gg - b * NG;
        const int base = g * GRP + lane * 4;
        const float* f0b = f0 + b * T_FRAMES;

        float inc[4], f0v[4], wfr[4];
        int   ia[4];
#pragma unroll
        for (int j = 0; j < 4; j++) {
            int i = base + j;
            float pos = fmaf((float)i + 0.5f, SCALE_POS, -0.5f);
            pos = fminf(fmaxf(pos, 0.0f), 1999.0f);
            int i0 = (int)pos;
            int i1 = min(i0 + 1, 1999);
            float w = pos - (float)i0;
            ia[j] = i0; wfr[j] = w;
            float v = f0b[i0] * (1.0f - w) + f0b[i1] * w;
            f0v[j] = v;
            inc[j] = v * INV_SR;
        }

        float inc4 = ((inc[0] + inc[1]) + inc[2]) + inc[3];
        float sv = inc4;
#pragma unroll
        for (int off = 1; off < 32; off <<= 1) {
            float n = __shfl_up_sync(FULL, sv, off);
            if (lane >= off) sv += n;
        }
        float running = g_carry[b * NG + g] + (sv - inc4);

        float4 nz = *(const float4*)(noise + (size_t)b * T_AUD + base);
        const float* nzp = &nz.x;

        float och[7][4];
#pragma unroll
        for (int j = 0; j < 4; j++) {
            running += inc[j];
            float r  = running - rintf(running);
            float s1, c1;
            __sincosf(TWO_PI_F * r, &s1, &c1);
            float voiced = (f0v[j] > 1.0f) ? 1.0f : 0.0f;

            const float* ap = g_amp + ((size_t)b * T_FRAMES + ia[j]) * 8;
            int i1 = min(ia[j] + 1, 1999);
            const float* aq = g_amp + ((size_t)b * T_FRAMES + i1) * 8;
            float4 u0 = *(const float4*)ap;
            float4 u1 = *(const float4*)(ap + 4);
            float4 p0 = *(const float4*)aq;
            float4 p1 = *(const float4*)(aq + 4);
            float w = wfr[j], iw = 1.0f - w;
            float am[6] = { u0.x * iw + p0.x * w, u0.y * iw + p0.y * w,
                            u0.z * iw + p0.z * w, u0.w * iw + p0.w * w,
                            u1.x * iw + p1.x * w, u1.y * iw + p1.y * w };

            float sk = s1, ck = c1;
#pragma unroll
            for (int h = 0; h < 6; h++) {
                if (h) {
                    float t = sk * c1 + ck * s1;
                    ck = ck * c1 - sk * s1;
                    sk = t;
                }
                float sig2 = 1.0f + tanh_approx(0.5f * am[h]);
                och[h][j] = (sk * cA[h] + ck * cB[h]) * (sig2 * voiced);
            }
            float na = (voiced > 0.0f) ? nvs : nus;
            och[6][j] = nzp[j] * na;
        }

#pragma unroll
        for (int h = 0; h < 7; h++) {
            float4 o = make_float4(och[h][0], och[h][1], och[h][2], och[h][3]);
            *(float4*)(out + ((size_t)(b * 7 + h)) * T_AUD + base) = o;
        }
    }
}

// ---------------- launcher ----------------
extern "C" void kernel_launch(void* const* d_in, const int* in_sizes, int n_in,
                              void* d_out, int out_size)
{
    const float* f0    = (const float*)d_in[0];
    const float* mel   = (const float*)d_in[1];
    const float* noise = (const float*)d_in[2];
    const float* w1    = (const float*)d_in[3];
    const float* b1    = (const float*)d_in[4];
    const float* w2    = (const float*)d_in[5];
    const float* b2    = (const float*)d_in[6];
    const float* als   = (const float*)d_in[7];
    const float* pho   = (const float*)d_in[8];
    const float* lnv   = (const float*)d_in[9];
    const float* lnu   = (const float*)d_in[10];
    float* out = (float*)d_out;

    fused_kernel<<<NBLOCKS, 256>>>(f0, mel, noise, w1, b1, w2, b2,
                                   als, pho, lnv, lnu, out);
}

// round 11
// speedup vs baseline: 1.5312x; 1.0446x over previous
#include <cuda_runtime.h>
#include <cuda_bf16.h>
#include <math.h>

#define T_FRAMES 2000
#define NB 4
#define NHARM 6
#define T_AUD 960000
#define GRP 128
#define NG 7500                  // 128-sample groups per batch
#define NGTOT 30000
#define SCALE_POS (2000.0f/960000.0f)
#define INV_SR (1.0f/48000.0f)
#define TWO_PI_F 6.2831853071795864769f

#define NBLOCKS 296              // 2 per SM x 148: single wave, all resident
#define NTHREADS 512
#define NWARPS_G (NBLOCKS * 16)  // 4736
#define CONV_NB 126              // 252 tiles (32 frames), 2 per block
#define W1_ELEMS (32 * 129 * 5)  // 20640

// ---------------- scratch ----------------
__device__ float  g_amp[NB * T_FRAMES * 8];  // [b][t][8], ch 0..5 valid
__device__ float4 g_w4[129 * 32];            // w1 k=0..3, [ic][c]
__device__ float  g_w1s[129 * 32];           // w1 k=4,    [ic][c]
__device__ float  g_tot[NB * NG];
__device__ float  g_carry[NB * NG];
__device__ float  g_consts[16];              // [0..5]=A, [6..11]=B
__device__ unsigned g_cnt;                   // barrier counter (returns to 0)
__device__ volatile unsigned g_sense;        // barrier sense (returns to 0)

__device__ __forceinline__ float tanh_approx(float x) {
    float y;
    asm("tanh.approx.f32 %0, %1;" : "=f"(y) : "f"(x));
    return y;
}

__device__ __forceinline__ void grid_barrier(unsigned target) {
    __syncthreads();
    if (threadIdx.x == 0) {
        __threadfence();
        unsigned old = atomicAdd(&g_cnt, 1u);
        if (old == NBLOCKS - 1) {
            *(volatile unsigned*)&g_cnt = 0u;
            __threadfence();
            g_sense = target;
        } else {
            while (g_sense != target) __nanosleep(32);
            __threadfence();
        }
    }
    __syncthreads();
}

__global__ void __launch_bounds__(NTHREADS, 2) fused_kernel(
    const float* __restrict__ f0, const float* __restrict__ mel,
    const float* __restrict__ noise,
    const float* __restrict__ w1, const float* __restrict__ b1,
    const float* __restrict__ w2, const float* __restrict__ b2,
    const float* __restrict__ als, const float* __restrict__ pho,
    const float* __restrict__ lnv, const float* __restrict__ lnu,
    float* __restrict__ out)
{
    __shared__ float  sxx[2][129 * 36];
    __shared__ float  sh[2][32 * 32];
    __shared__ double wsum[16];

    const int bid  = blockIdx.x;
    const int tid  = threadIdx.x;
    const int wid  = tid >> 5;
    const int lane = tid & 31;
    const unsigned FULL = 0xffffffffu;

    // ================= PHASE 1: totals + noise channel + transpose + consts ========
    if (bid < 41) {
        int e = bid * NTHREADS + tid;
        if (e < W1_ELEMS) {
            int c  = e / 645;
            int r  = e - c * 645;
            int ic = r / 5;
            int k  = r - ic * 5;
            float val = w1[e];
            if (k < 4) ((float*)g_w4)[(ic * 32 + c) * 4 + k] = val;
            else       g_w1s[ic * 32 + c] = val;
        }
    }
    if (bid == 100 && tid < NHARM) {
        float e  = expf(als[tid]);
        float ph = TWO_PI_F * pho[tid];
        g_consts[tid]     = e * cosf(ph);
        g_consts[6 + tid] = e * sinf(ph);
    }
    {
        const float nvs = __expf(lnv[0]);
        const float nus = __expf(lnu[0]);
        for (int gg = bid * 16 + wid; gg < NGTOT; gg += NWARPS_G) {
            int b = gg / NG;
            int g = gg - b * NG;
            const float* f0b = f0 + b * T_FRAMES;
            int base = g * GRP + lane * 4;
            float4 nz = *(const float4*)(noise + (size_t)b * T_AUD + base);
            const float* nzp = &nz.x;
            float o4[4];
            float s = 0.0f;
#pragma unroll
            for (int j = 0; j < 4; j++) {
                int i = base + j;
                float pos = fmaf((float)i + 0.5f, SCALE_POS, -0.5f);
                pos = fminf(fmaxf(pos, 0.0f), 1999.0f);
                int i0 = (int)pos;
                int i1 = min(i0 + 1, 1999);
                float w = pos - (float)i0;
                float v = f0b[i0] * (1.0f - w) + f0b[i1] * w;
                s += v * INV_SR;
                o4[j] = nzp[j] * ((v > 1.0f) ? nvs : nus);
            }
            *(float4*)(out + (size_t)(b * 7 + 6) * T_AUD + base) =
                make_float4(o4[0], o4[1], o4[2], o4[3]);
#pragma unroll
            for (int off = 16; off; off >>= 1)
                s += __shfl_down_sync(FULL, s, off);
            if (lane == 0) g_tot[b * NG + g] = s;
        }
    }

    grid_barrier(1u);

    // ================= PHASE 2: conv (126 blocks x 2 tiles) || scan (4 blocks) =====
    if (bid < CONV_NB) {
        const int harr = tid >> 8;          // half-block 0/1
        const int htid = tid & 255;
        const int tile = bid * 2 + harr;    // 0..251
        const int b    = tile / 63;
        const int t0   = (tile - b * 63) * 32;
        float* sx = sxx[harr];
        float* shh = sh[harr];

        for (int e = htid; e < 129 * 36; e += 256) {
            int ic = e / 36, tt = e - ic * 36;
            int t = t0 + tt - 2;
            float v = 0.0f;
            if (t >= 0 && t < T_FRAMES)
                v = (ic == 0) ? f0[b * T_FRAMES + t]
                              : mel[(b * 128 + (ic - 1)) * T_FRAMES + t];
            sx[e] = v;
        }
        __syncthreads();

        const int c  = htid & 31;           // channel = lane
        const int tb = (htid >> 5) * 4;     // frames tb..tb+3

        float acc0, acc1, acc2, acc3;
        acc0 = acc1 = acc2 = acc3 = b1[c];

#pragma unroll 3
        for (int ic = 0; ic < 129; ic++) {
            float4 wa = __ldg(&g_w4[ic * 32 + c]);
            float  w4 = __ldg(&g_w1s[ic * 32 + c]);
            float4 xa = *(const float4*)&sx[ic * 36 + tb];
            float4 xb = *(const float4*)&sx[ic * 36 + tb + 4];
            acc0 = fmaf(wa.x, xa.x, acc0); acc0 = fmaf(wa.y, xa.y, acc0);
            acc0 = fmaf(wa.z, xa.z, acc0); acc0 = fmaf(wa.w, xa.w, acc0);
            acc0 = fmaf(w4,  xb.x, acc0);
            acc1 = fmaf(wa.x, xa.y, acc1); acc1 = fmaf(wa.y, xa.z, acc1);
            acc1 = fmaf(wa.z, xa.w, acc1); acc1 = fmaf(wa.w, xb.x, acc1);
            acc1 = fmaf(w4,  xb.y, acc1);
            acc2 = fmaf(wa.x, xa.z, acc2); acc2 = fmaf(wa.y, xa.w, acc2);
            acc2 = fmaf(wa.z, xb.x, acc2); acc2 = fmaf(wa.w, xb.y, acc2);
            acc2 = fmaf(w4,  xb.z, acc2);
            acc3 = fmaf(wa.x, xa.w, acc3); acc3 = fmaf(wa.y, xb.x, acc3);
            acc3 = fmaf(wa.z, xb.y, acc3); acc3 = fmaf(wa.w, xb.z, acc3);
            acc3 = fmaf(w4,  xb.w, acc3);
        }
        shh[c * 32 + tb + 0] = acc0 / (1.0f + __expf(-acc0));
        shh[c * 32 + tb + 1] = acc1 / (1.0f + __expf(-acc1));
        shh[c * 32 + tb + 2] = acc2 / (1.0f + __expf(-acc2));
        shh[c * 32 + tb + 3] = acc3 / (1.0f + __expf(-acc3));
        __syncthreads();

        if (htid < NHARM * 32) {
            int nh = htid >> 5, tl = htid & 31;
            int t = t0 + tl;
            if (t < T_FRAMES) {
                float s = b2[nh];
                const float* wp = &w2[nh * 32];
#pragma unroll
                for (int cc = 0; cc < 32; cc++)
                    s = fmaf(__ldg(wp + cc), shh[cc * 32 + tl], s);
                g_amp[((size_t)b * T_FRAMES + t) * 8 + nh] = s;
            }
        }
    } else if (bid < CONV_NB + NB) {
        // ---- scan role: one block per batch, 512 threads, PER=15 ----
        const int b = bid - CONV_NB;
        const int PER = 15;                 // 512*15 >= 7500
        const int s0 = tid * PER;
        float tl[PER];
        double loc = 0.0;
#pragma unroll
        for (int j = 0; j < PER; j++) {
            int idx = s0 + j;
            float t = (idx < NG) ? g_tot[b * NG + idx] : 0.0f;
            tl[j] = t;
            loc += (double)t;
        }
        double v = loc;
#pragma unroll
        for (int off = 1; off < 32; off <<= 1) {
            double n = __shfl_up_sync(FULL, v, off);
            if (lane >= off) v += n;
        }
        if (lane == 31) wsum[wid] = v;
        __syncthreads();
        if (wid == 0 && lane < 16) {
            double x = wsum[lane];
#pragma unroll
            for (int off = 1; off < 16; off <<= 1) {
                double n = __shfl_up_sync(0xffffu, x, off);
                if (lane >= off) x += n;
            }
            wsum[lane] = x;
        }
        __syncthreads();
        double base = (v - loc) + (wid ? wsum[wid - 1] : 0.0);
#pragma unroll
        for (int j = 0; j < PER; j++) {
            int idx = s0 + j;
            if (idx < NG)
                g_carry[b * NG + idx] = (float)(base - floor(base));
            base += (double)tl[j];
        }
    }

    grid_barrier(0u);

    // ================= PHASE 3: harmonic synthesis (channels 0..5) =================
    float cA[6], cB[6];
#pragma unroll
    for (int h = 0; h < 6; h++) { cA[h] = g_consts[h]; cB[h] = g_consts[6 + h]; }

    for (int gg = bid * 16 + wid; gg < NGTOT; gg += NWARPS_G) {
        const int b    = gg / NG;
        const int g    = gg - b * NG;
        const int base = g * GRP + lane * 4;
        const float* f0b = f0 + b * T_FRAMES;

        float inc[4], f0v[4], wfr[4];
        int   ia[4];
#pragma unroll
        for (int j = 0; j < 4; j++) {
            int i = base + j;
            float pos = fmaf((float)i + 0.5f, SCALE_POS, -0.5f);
            pos = fminf(fmaxf(pos, 0.0f), 1999.0f);
            int i0 = (int)pos;
            int i1 = min(i0 + 1, 1999);
            float w = pos - (float)i0;
            ia[j] = i0; wfr[j] = w;
            float v = f0b[i0] * (1.0f - w) + f0b[i1] * w;
            f0v[j] = v;
            inc[j] = v * INV_SR;
        }

        float inc4 = ((inc[0] + inc[1]) + inc[2]) + inc[3];
        float sv = inc4;
#pragma unroll
        for (int off = 1; off < 32; off <<= 1) {
            float n = __shfl_up_sync(FULL, sv, off);
            if (lane >= off) sv += n;
        }
        float running = g_carry[b * NG + g] + (sv - inc4);

        float och[6][4];
#pragma unroll
        for (int j = 0; j < 4; j++) {
            running += inc[j];
            float r  = running - rintf(running);
            float s1, c1;
            __sincosf(TWO_PI_F * r, &s1, &c1);
            float voiced = (f0v[j] > 1.0f) ? 1.0f : 0.0f;

            const float* ap = g_amp + ((size_t)b * T_FRAMES + ia[j]) * 8;
            int i1 = min(ia[j] + 1, 1999);
            const float* aq = g_amp + ((size_t)b * T_FRAMES + i1) * 8;
            float4 u0 = *(const float4*)ap;
            float4 u1 = *(const float4*)(ap + 4);
            float4 p0 = *(const float4*)aq;
            float4 p1 = *(const float4*)(aq + 4);
            float w = wfr[j], iw = 1.0f - w;
            float am[6] = { u0.x * iw + p0.x * w, u0.y * iw + p0.y * w,
                            u0.z * iw + p0.z * w, u0.w * iw + p0.w * w,
                            u1.x * iw + p1.x * w, u1.y * iw + p1.y * w };

            float sk = s1, ck = c1;
#pragma unroll
            for (int h = 0; h < 6; h++) {
                if (h) {
                    float t = sk * c1 + ck * s1;
                    ck = ck * c1 - sk * s1;
                    sk = t;
                }
                float sig2 = 1.0f + tanh_approx(0.5f * am[h]);
                och[h][j] = (sk * cA[h] + ck * cB[h]) * (sig2 * voiced);
            }
        }

#pragma unroll
        for (int h = 0; h < 6; h++) {
            float4 o = make_float4(och[h][0], och[h][1], och[h][2], och[h][3]);
            *(float4*)(out + ((size_t)(b * 7 + h)) * T_AUD + base) = o;
        }
    }
}

// ---------------- launcher ----------------
extern "C" void kernel_launch(void* const* d_in, const int* in_sizes, int n_in,
                              void* d_out, int out_size)
{
    const float* f0    = (const float*)d_in[0];
    const float* mel   = (const float*)d_in[1];
    const float* noise = (const float*)d_in[2];
    const float* w1    = (const float*)d_in[3];
    const float* b1    = (const float*)d_in[4];
    const float* w2    = (const float*)d_in[5];
    const float* b2    = (const float*)d_in[6];
    const float* als   = (const float*)d_in[7];
    const float* pho   = (const float*)d_in[8];
    const float* lnv   = (const float*)d_in[9];
    const float* lnu   = (const float*)d_in[10];
    float* out = (float*)d_out;

    fused_kernel<<<NBLOCKS, NTHREADS>>>(f0, mel, noise, w1, b1, w2, b2,
                                        als, pho, lnv, lnu, out);
}

// round 12
// speedup vs baseline: 1.5921x; 1.0398x over previous
#include <cuda_runtime.h>
#include <cuda_bf16.h>
#include <math.h>

#define T_FRAMES 2000
#define NB 4
#define NHARM 6
#define T_AUD 960000
#define GRP 128
#define NG 7500                  // 128-sample groups per batch
#define NGTOT 30000
#define SCALE_POS (2000.0f/960000.0f)
#define INV_SR (1.0f/48000.0f)
#define TWO_PI_F 6.2831853071795864769f

#define NBLOCKS 296              // 2 per SM x 148: single wave, all resident
#define NTHREADS 512
#define NWARPS_G (NBLOCKS * 16)  // 4736
#define CONV_NB 252              // one 32-frame tile per block
#define W1_ELEMS (32 * 129 * 5)  // 20640

// ---------------- scratch ----------------
__device__ float  g_amp[NB * T_FRAMES * 8];  // [b][t][8], ch 0..5 valid
__device__ float4 g_w4[129 * 32];            // w1 k=0..3, [ic][c]
__device__ float  g_w1s[129 * 32];           // w1 k=4,    [ic][c]
__device__ float  g_tot[NB * NG];
__device__ float  g_carry[NB * NG];
__device__ float  g_consts[16];              // [0..5]=A, [6..11]=B
__device__ unsigned g_cnt;                   // barrier counter (returns to 0)
__device__ volatile unsigned g_sense;        // barrier sense (returns to 0)

__device__ __forceinline__ float tanh_approx(float x) {
    float y;
    asm("tanh.approx.f32 %0, %1;" : "=f"(y) : "f"(x));
    return y;
}

__device__ __forceinline__ void grid_barrier(unsigned target) {
    __syncthreads();
    if (threadIdx.x == 0) {
        __threadfence();
        unsigned old = atomicAdd(&g_cnt, 1u);
        if (old == NBLOCKS - 1) {
            *(volatile unsigned*)&g_cnt = 0u;
            __threadfence();
            g_sense = target;
        } else {
            while (g_sense != target) __nanosleep(32);
            __threadfence();
        }
    }
    __syncthreads();
}

__global__ void __launch_bounds__(NTHREADS, 2) fused_kernel(
    const float* __restrict__ f0, const float* __restrict__ mel,
    const float* __restrict__ noise,
    const float* __restrict__ w1, const float* __restrict__ b1,
    const float* __restrict__ w2, const float* __restrict__ b2,
    const float* __restrict__ als, const float* __restrict__ pho,
    const float* __restrict__ lnv, const float* __restrict__ lnu,
    float* __restrict__ out)
{
    __shared__ float  sxx[129 * 36];
    __shared__ float  sh[32 * 32];
    __shared__ double wsum[16];

    const int bid  = blockIdx.x;
    const int tid  = threadIdx.x;
    const int wid  = tid >> 5;
    const int lane = tid & 31;
    const unsigned FULL = 0xffffffffu;

    // ================= PHASE 1: totals + noise channel + transpose + consts ========
    if (bid < 41) {
        int e = bid * NTHREADS + tid;
        if (e < W1_ELEMS) {
            int c  = e / 645;
            int r  = e - c * 645;
            int ic = r / 5;
            int k  = r - ic * 5;
            float val = w1[e];
            if (k < 4) ((float*)g_w4)[(ic * 32 + c) * 4 + k] = val;
            else       g_w1s[ic * 32 + c] = val;
        }
    }
    if (bid == 100 && tid < NHARM) {
        float e  = expf(als[tid]);
        float ph = TWO_PI_F * pho[tid];
        g_consts[tid]     = e * cosf(ph);
        g_consts[6 + tid] = e * sinf(ph);
    }
    {
        const float nvs = __expf(lnv[0]);
        const float nus = __expf(lnu[0]);
        for (int gg = bid * 16 + wid; gg < NGTOT; gg += NWARPS_G) {
            int b = gg / NG;
            int g = gg - b * NG;
            const float* f0b = f0 + b * T_FRAMES;
            int base = g * GRP + lane * 4;
            float4 nz = *(const float4*)(noise + (size_t)b * T_AUD + base);
            const float* nzp = &nz.x;
            float o4[4];
            float s = 0.0f;
#pragma unroll
            for (int j = 0; j < 4; j++) {
                int i = base + j;
                float pos = fmaf((float)i + 0.5f, SCALE_POS, -0.5f);
                pos = fminf(fmaxf(pos, 0.0f), 1999.0f);
                int i0 = (int)pos;
                int i1 = min(i0 + 1, 1999);
                float w = pos - (float)i0;
                float v = f0b[i0] * (1.0f - w) + f0b[i1] * w;
                s += v * INV_SR;
                o4[j] = nzp[j] * ((v > 1.0f) ? nvs : nus);
            }
            *(float4*)(out + (size_t)(b * 7 + 6) * T_AUD + base) =
                make_float4(o4[0], o4[1], o4[2], o4[3]);
#pragma unroll
            for (int off = 16; off; off >>= 1)
                s += __shfl_down_sync(FULL, s, off);
            if (lane == 0) g_tot[b * NG + g] = s;
        }
    }

    grid_barrier(1u);

    // ================= PHASE 2: conv (252 blocks, 1 tile each) || scan (4 blocks) ==
    if (bid < CONV_NB) {
        const int b  = bid / 63;
        const int t0 = (bid - b * 63) * 32;

        for (int e = tid; e < 129 * 36; e += NTHREADS) {
            int ic = e / 36, tt = e - ic * 36;
            int t = t0 + tt - 2;
            float v = 0.0f;
            if (t >= 0 && t < T_FRAMES)
                v = (ic == 0) ? f0[b * T_FRAMES + t]
                              : mel[(b * 128 + (ic - 1)) * T_FRAMES + t];
            sxx[e] = v;
        }
        __syncthreads();

        const int c  = tid & 31;            // channel = lane -> coalesced weight LDG
        const int tb = (tid >> 5) * 2;      // frames tb, tb+1 (warp-uniform)

        float acc0, acc1;
        acc0 = acc1 = b1[c];

#pragma unroll 4
        for (int ic = 0; ic < 129; ic++) {
            float4 wa = __ldg(&g_w4[ic * 32 + c]);
            float  w4 = __ldg(&g_w1s[ic * 32 + c]);
            float2 xa = *(const float2*)&sxx[ic * 36 + tb];
            float2 xb = *(const float2*)&sxx[ic * 36 + tb + 2];
            float2 xc = *(const float2*)&sxx[ic * 36 + tb + 4];
            acc0 = fmaf(wa.x, xa.x, acc0); acc0 = fmaf(wa.y, xa.y, acc0);
            acc0 = fmaf(wa.z, xb.x, acc0); acc0 = fmaf(wa.w, xb.y, acc0);
            acc0 = fmaf(w4,  xc.x, acc0);
            acc1 = fmaf(wa.x, xa.y, acc1); acc1 = fmaf(wa.y, xb.x, acc1);
            acc1 = fmaf(wa.z, xb.y, acc1); acc1 = fmaf(wa.w, xc.x, acc1);
            acc1 = fmaf(w4,  xc.y, acc1);
        }
        sh[c * 32 + tb + 0] = acc0 / (1.0f + __expf(-acc0));
        sh[c * 32 + tb + 1] = acc1 / (1.0f + __expf(-acc1));
        __syncthreads();

        if (tid < NHARM * 32) {
            int nh = tid >> 5, tl = tid & 31;
            int t = t0 + tl;
            if (t < T_FRAMES) {
                float s = b2[nh];
                const float* wp = &w2[nh * 32];
#pragma unroll
                for (int cc = 0; cc < 32; cc++)
                    s = fmaf(__ldg(wp + cc), sh[cc * 32 + tl], s);
                g_amp[((size_t)b * T_FRAMES + t) * 8 + nh] = s;
            }
        }
    } else if (bid < CONV_NB + NB) {
        // ---- scan role: one block per batch, 512 threads, PER=15 ----
        const int b = bid - CONV_NB;
        const int PER = 15;                 // 512*15 >= 7500
        const int s0 = tid * PER;
        float tl[PER];
        double loc = 0.0;
#pragma unroll
        for (int j = 0; j < PER; j++) {
            int idx = s0 + j;
            float t = (idx < NG) ? g_tot[b * NG + idx] : 0.0f;
            tl[j] = t;
            loc += (double)t;
        }
        double v = loc;
#pragma unroll
        for (int off = 1; off < 32; off <<= 1) {
            double n = __shfl_up_sync(FULL, v, off);
            if (lane >= off) v += n;
        }
        if (lane == 31) wsum[wid] = v;
        __syncthreads();
        if (wid == 0 && lane < 16) {
            double x = wsum[lane];
#pragma unroll
            for (int off = 1; off < 16; off <<= 1) {
                double n = __shfl_up_sync(0xffffu, x, off);
                if (lane >= off) x += n;
            }
            wsum[lane] = x;
        }
        __syncthreads();
        double base = (v - loc) + (wid ? wsum[wid - 1] : 0.0);
#pragma unroll
        for (int j = 0; j < PER; j++) {
            int idx = s0 + j;
            if (idx < NG)
                g_carry[b * NG + idx] = (float)(base - floor(base));
            base += (double)tl[j];
        }
    }

    grid_barrier(0u);

    // ================= PHASE 3: harmonic synthesis (channels 0..5) =================
    float cA[6], cB[6];
#pragma unroll
    for (int h = 0; h < 6; h++) { cA[h] = g_consts[h]; cB[h] = g_consts[6 + h]; }

    for (int gg = bid * 16 + wid; gg < NGTOT; gg += NWARPS_G) {
        const int b    = gg / NG;
        const int g    = gg - b * NG;
        const int base = g * GRP + lane * 4;
        const float* f0b = f0 + b * T_FRAMES;

        float inc[4], f0v[4], wfr[4];
        int   ia[4];
#pragma unroll
        for (int j = 0; j < 4; j++) {
            int i = base + j;
            float pos = fmaf((float)i + 0.5f, SCALE_POS, -0.5f);
            pos = fminf(fmaxf(pos, 0.0f), 1999.0f);
            int i0 = (int)pos;
            int i1 = min(i0 + 1, 1999);
            float w = pos - (float)i0;
            ia[j] = i0; wfr[j] = w;
            float v = f0b[i0] * (1.0f - w) + f0b[i1] * w;
            f0v[j] = v;
            inc[j] = v * INV_SR;
        }

        float inc4 = ((inc[0] + inc[1]) + inc[2]) + inc[3];
        float sv = inc4;
#pragma unroll
        for (int off = 1; off < 32; off <<= 1) {
            float n = __shfl_up_sync(FULL, sv, off);
            if (lane >= off) sv += n;
        }
        float running = g_carry[b * NG + g] + (sv - inc4);

        float och[6][4];
#pragma unroll
        for (int j = 0; j < 4; j++) {
            running += inc[j];
            float s1, c1;
            __sincosf(TWO_PI_F * running, &s1, &c1);
            float voiced = (f0v[j] > 1.0f) ? 1.0f : 0.0f;

            const float* ap = g_amp + ((size_t)b * T_FRAMES + ia[j]) * 8;
            int i1 = min(ia[j] + 1, 1999);
            const float* aq = g_amp + ((size_t)b * T_FRAMES + i1) * 8;
            float4 u0 = *(const float4*)ap;
            float4 u1 = *(const float4*)(ap + 4);
            float4 p0 = *(const float4*)aq;
            float4 p1 = *(const float4*)(aq + 4);
            float w = wfr[j], iw = 1.0f - w;
            float am[6] = { u0.x * iw + p0.x * w, u0.y * iw + p0.y * w,
                            u0.z * iw + p0.z * w, u0.w * iw + p0.w * w,
                            u1.x * iw + p1.x * w, u1.y * iw + p1.y * w };

            float sk = s1, ck = c1;
#pragma unroll
            for (int h = 0; h < 6; h++) {
                if (h) {
                    float t = sk * c1 + ck * s1;
                    ck = ck * c1 - sk * s1;
                    sk = t;
                }
                float sig2 = 1.0f + tanh_approx(0.5f * am[h]);
                och[h][j] = (sk * cA[h] + ck * cB[h]) * (sig2 * voiced);
            }
        }

#pragma unroll
        for (int h = 0; h < 6; h++) {
            float4 o = make_float4(och[h][0], och[h][1], och[h][2], och[h][3]);
            *(float4*)(out + ((size_t)(b * 7 + h)) * T_AUD + base) = o;
        }
    }
}

// ---------------- launcher ----------------
extern "C" void kernel_launch(void* const* d_in, const int* in_sizes, int n_in,
                              void* d_out, int out_size)
{
    const float* f0    = (const float*)d_in[0];
    const float* mel   = (const float*)d_in[1];
    const float* noise = (const float*)d_in[2];
    const float* w1    = (const float*)d_in[3];
    const float* b1    = (const float*)d_in[4];
    const float* w2    = (const float*)d_in[5];
    const float* b2    = (const float*)d_in[6];
    const float* als   = (const float*)d_in[7];
    const float* pho   = (const float*)d_in[8];
    const float* lnv   = (const float*)d_in[9];
    const float* lnu   = (const float*)d_in[10];
    float* out = (float*)d_out;

    fused_kernel<<<NBLOCKS, NTHREADS>>>(f0, mel, noise, w1, b1, w2, b2,
                                        als, pho, lnv, lnu, out);
}